// round 7
// baseline (speedup 1.0000x reference)
#include <cuda_runtime.h>
#include <math.h>

#define LSEQ   8192
#define NBATCH 1024
#define NTC    1024        // threads per conv/kprep block
#define NSTATE 64
#define PI_D 3.14159265358979323846

// Skewed smem layout: 1 pad float2 per 8 -> kills stride-64B store conflicts
#define PD(i) ((i) + ((i) >> 3))
#define PDSZ 9216          // PD(8191)=9214 < 9216

__device__ float2 g_wm[16384];   // WM[k] = exp(-2*pi*i*k/16384)
__device__ float2 g_kh[4100];    // K_hat spectrum bins 0..4096
__device__ float2 g_kf[8200];    // rfft_16384 of padded K, bins 0..8192

// ---------------- complex helpers ----------------
static __device__ __forceinline__ float2 cmul(float2 a, float2 b) {
    return make_float2(a.x*b.x - a.y*b.y, a.x*b.y + a.y*b.x);
}
static __device__ __forceinline__ float2 cadd(float2 a, float2 b){ return make_float2(a.x+b.x, a.y+b.y); }
static __device__ __forceinline__ float2 csub(float2 a, float2 b){ return make_float2(a.x-b.x, a.y-b.y); }
static __device__ __forceinline__ float2 cconj(float2 a){ return make_float2(a.x, -a.y); }
static __device__ __forceinline__ float2 cscale(float2 a, float s){ return make_float2(a.x*s, a.y*s); }

// ---------------- merged setup: twiddle table + Cauchy K_hat ----------------
// blocks 0..4096: khat (64 thr). blocks 4097..4352: twiddle init (64 thr).
__global__ void setup_kernel(const float* __restrict__ Bv, const float* __restrict__ Cv) {
    if (blockIdx.x > 4096) {
        int k = (blockIdx.x - 4097) * 64 + threadIdx.x;   // 0..16383
        double s, c;
        sincospi((double)k / 8192.0, &s, &c);
        g_wm[k] = make_float2((float)c, (float)(-s));
        return;
    }
    __shared__ double shg[5];
    __shared__ double wsum[2][8];
    int f = blockIdx.x;              // 0..4096
    int n = threadIdx.x;             // 0..63
    if (n == 0) {
        // sincos, NOT sincospi: sincospi(1.0) gives exactly (0,-1) -> 1+omega==0
        // -> NaN at Nyquist. sincos keeps the bin finite (s~1.2e-16).
        double th = (2.0 * PI_D / 8192.0) * (double)f;
        double s, c;
        sincos(th, &s, &c);
        double nr = 1.0 - c, ni = -s;
        double dr = 1.0 + c, di = s;
        double dd = dr*dr + di*di;
        shg[0] = 20.0 * (nr*dr + ni*di) / dd;
        shg[1] = 20.0 * (ni*dr - nr*di) / dd;
        shg[2] = dr; shg[3] = di; shg[4] = dd;
    }
    __syncthreads();
    double gr = shg[0], gi = shg[1];
    double er = gr + 0.5;
    double ei = gi - PI_D * (double)n;
    double inv = 1.0 / (er*er + ei*ei);
    double ir =  er * inv, ii = -ei * inv;
    double b0 = (double)Bv[n];
    double a0 = (double)Cv[n];
    double p2 = (double)n + 0.5;
    double p  = sqrt(p2);
    double v00 = a0*b0, v01 = a0*p, v10 = p*b0, v11 = p2;
    double acc[8] = { v00*ir, v00*ii, v01*ir, v01*ii,
                      v10*ir, v10*ii, v11*ir, v11*ii };
    #pragma unroll
    for (int off = 16; off; off >>= 1) {
        #pragma unroll
        for (int t = 0; t < 8; t++)
            acc[t] += __shfl_down_sync(0xffffffffu, acc[t], off);
    }
    if ((n & 31) == 0) {
        #pragma unroll
        for (int t = 0; t < 8; t++) wsum[n >> 5][t] = acc[t];
    }
    __syncthreads();
    if (n == 0) {
        double k00r = wsum[0][0]+wsum[1][0], k00i = wsum[0][1]+wsum[1][1];
        double k01r = wsum[0][2]+wsum[1][2], k01i = wsum[0][3]+wsum[1][3];
        double k10r = wsum[0][4]+wsum[1][4], k10i = wsum[0][5]+wsum[1][5];
        double k11r = wsum[0][6]+wsum[1][6], k11i = wsum[0][7]+wsum[1][7];
        double ur = 1.0 + k11r, ui = k11i;
        double t1r = k01r*ur - k01i*ui, t1i = k01r*ui + k01i*ur;
        double t2r = t1r*k10r - t1i*k10i, t2i = t1r*k10i + t1i*k10r;
        double hr = k00r - t2r, hi = k00i - t2i;
        double dr = shg[2], di = shg[3], dd = shg[4];
        double c2r = 2.0*dr/dd, c2i = -2.0*di/dd;
        g_kh[f] = make_float2((float)(c2r*hr - c2i*hi), (float)(c2r*hi + c2i*hr));
    }
}

// ---------------- radix-8 Stockham FFT, N=8192, forward, skewed smem ----------------
// 4 radix-8 stages + final radix-2. Reads A (PD layout), result in B (PD layout).
// ZHI: input's upper half (idx>=4096) is known zero. SKIPHI: skip storing outputs [4096,8192).
template<int NTH, bool ZHI, bool SKIPHI>
static __device__ __forceinline__ void fft8192_r8(float2* A, float2* B, int tid) {
    float2* src = A;
    float2* dst = B;
    #pragma unroll
    for (int st = 0; st < 4; st++) {
        const int ls = 3 * st;            // log2(s): 0,3,6,9
        const int s  = 1 << ls;           // 1,8,64,512
        #pragma unroll
        for (int it = 0; it < 1024 / NTH; it++) {
            int idx = tid + it * NTH;     // < 1024
            int p = idx >> ls;
            int q = idx & (s - 1);
            float2 x0 = src[PD(idx)];
            float2 x1 = src[PD(idx + 1024)];
            float2 x2 = src[PD(idx + 2048)];
            float2 x3 = src[PD(idx + 3072)];
            float2 x4, x5, x6, x7;
            if (ZHI && st == 0) {
                x4 = x5 = x6 = x7 = make_float2(0.f, 0.f);
            } else {
                x4 = src[PD(idx + 4096)];
                x5 = src[PD(idx + 5120)];
                x6 = src[PD(idx + 6144)];
                x7 = src[PD(idx + 7168)];
            }
            // DFT8
            float2 ea = cadd(x0, x4), em = csub(x0, x4);
            float2 eb = cadd(x2, x6), en = csub(x2, x6);
            float2 ej = make_float2(-en.y, en.x);
            float2 E0 = cadd(ea, eb), E1 = csub(em, ej);
            float2 E2 = csub(ea, eb), E3 = cadd(em, ej);
            float2 oa = cadd(x1, x5), om = csub(x1, x5);
            float2 ob = cadd(x3, x7), on = csub(x3, x7);
            float2 oj = make_float2(-on.y, on.x);
            float2 O0 = cadd(oa, ob), O1 = csub(om, oj);
            float2 O2 = csub(oa, ob), O3 = cadd(om, oj);
            const float C = 0.70710678118654752440f;
            float2 t0 = O0;
            float2 t1 = make_float2(C*(O1.x + O1.y), C*(O1.y - O1.x));
            float2 t2 = make_float2(O2.y, -O2.x);
            float2 t3 = make_float2(C*(O3.y - O3.x), -C*(O3.x + O3.y));
            float2 X0 = cadd(E0, t0), X4 = csub(E0, t0);
            float2 X1 = cadd(E1, t1), X5 = csub(E1, t1);
            float2 X2 = cadd(E2, t2), X6 = csub(E2, t2);
            float2 X3 = cadd(E3, t3), X7 = csub(E3, t3);
            // twiddles w_j = exp(-2*pi*i*p*s*j/8192) = g_wm[2*p*s*j]
            int tw = (p << (ls + 1));
            float2 w1 = g_wm[tw];
            float2 w2 = cmul(w1, w1);
            float2 w3 = cmul(w2, w1);
            float2 w4 = cmul(w2, w2);
            float2 w5 = cmul(w3, w2);
            float2 w6 = cmul(w3, w3);
            float2 w7 = cmul(w4, w3);
            int o = q + (p << (ls + 3));
            dst[PD(o)]       = X0;
            dst[PD(o + s)]   = cmul(w1, X1);
            dst[PD(o + 2*s)] = cmul(w2, X2);
            dst[PD(o + 3*s)] = cmul(w3, X3);
            dst[PD(o + 4*s)] = cmul(w4, X4);
            dst[PD(o + 5*s)] = cmul(w5, X5);
            dst[PD(o + 6*s)] = cmul(w6, X6);
            dst[PD(o + 7*s)] = cmul(w7, X7);
        }
        __syncthreads();
        float2* t = src; src = dst; dst = t;
    }
    // After 4 swaps: src == A, dst == B. Final radix-2 (p=0, twiddle-free).
    #pragma unroll
    for (int it = 0; it < 4096 / NTH; it++) {
        int q = tid + it * NTH;
        float2 a = src[PD(q)], b = src[PD(q + 4096)];
        dst[PD(q)] = cadd(a, b);
        if (!SKIPHI) dst[PD(q + 4096)] = csub(a, b);
    }
    __syncthreads();
}

// ---------------- K preparation (1 block, 1024 threads) ----------------
__global__ void __launch_bounds__(NTC, 1) kprep_kernel() {
    extern __shared__ float2 sm[];
    float2* A = sm;
    float2* B = sm + PDSZ;
    int tid = threadIdx.x;

    // Hermitian-extend K_hat and conjugate (conj trick for inverse FFT)
    for (int f = tid; f < 8192; f += NTC) {
        float2 kh = (f <= 4096) ? g_kh[f] : g_kh[8192 - f];
        A[PD(f)] = (f <= 4096) ? cconj(kh) : kh;
    }
    __syncthreads();
    fft8192_r8<NTC, false, false>(A, B, tid);
    // K[t] = B[t].x/8192 ; pack halves into complex (upper half zero -> ZHI)
    const float sc = 1.0f / 8192.0f;
    for (int j = tid; j < 4096; j += NTC)
        A[PD(j)] = make_float2(B[PD(2*j)].x * sc, B[PD(2*j + 1)].x * sc);
    __syncthreads();
    fft8192_r8<NTC, true, false>(A, B, tid);
    // Unpack to rfft_16384 bins 0..8192
    for (int k = tid; k <= 4096; k += NTC) {
        if (k == 0) {
            float2 Z0 = B[PD(0)];
            g_kf[0]    = make_float2(Z0.x + Z0.y, 0.f);
            g_kf[8192] = make_float2(Z0.x - Z0.y, 0.f);
        } else {
            int hk = 8192 - k;
            float2 Zk  = B[PD(k)];
            float2 Zhc = cconj(B[PD(hk)]);
            float2 E  = cscale(cadd(Zk, Zhc), 0.5f);
            float2 Om = csub(Zk, Zhc);
            float2 O  = make_float2(0.5f * Om.y, -0.5f * Om.x);
            float2 w  = g_wm[k];
            g_kf[k] = cadd(E, cmul(w, O));
            if (k != 4096) {
                float2 wh = make_float2(-w.x, w.y);
                g_kf[hk] = cadd(cconj(E), cmul(wh, cconj(O)));
            }
        }
    }
}

// ---------------- main batched FFT convolution ----------------
__global__ void __launch_bounds__(NTC, 1) conv_kernel(const float* __restrict__ x,
                                                      float* __restrict__ y) {
    extern __shared__ float2 sm[];
    float2* A = sm;
    float2* B = sm + PDSZ;
    int b = blockIdx.x;
    int tid = threadIdx.x;

    // pack two reals per complex; upper half unwritten (ZHI FFT skips it)
    const float2* xr = (const float2*)(x + (size_t)b * LSEQ);
    for (int j = tid; j < 4096; j += NTC)
        A[PD(j)] = xr[j];
    __syncthreads();

    fft8192_r8<NTC, true, false>(A, B, tid);   // Z in B

    // unpack -> multiply by Kf -> repack conj(Zy) into A
    for (int k = tid; k <= 4096; k += NTC) {
        if (k == 0) {
            float2 Z0 = B[PD(0)];
            float X0 = Z0.x + Z0.y;
            float XH = Z0.x - Z0.y;
            float2 Y0 = cscale(g_kf[0], X0);
            float2 YH = cscale(g_kf[8192], XH);
            float2 Yhc = cconj(YH);
            float2 S = cscale(cadd(Y0, Yhc), 0.5f);
            float2 D = cscale(csub(Y0, Yhc), 0.5f);
            float2 Zy0 = make_float2(S.x - D.y, S.y + D.x);
            A[PD(0)] = cconj(Zy0);
        } else {
            int hk = 8192 - k;
            float2 Zk  = B[PD(k)];
            float2 Zhc = cconj(B[PD(hk)]);
            float2 E  = cscale(cadd(Zk, Zhc), 0.5f);
            float2 Om = csub(Zk, Zhc);
            float2 O  = make_float2(0.5f * Om.y, -0.5f * Om.x);
            float2 w  = g_wm[k];
            float2 Xk = cadd(E, cmul(w, O));
            float2 wh = make_float2(-w.x, w.y);
            float2 Xh = cadd(cconj(E), cmul(wh, cconj(O)));
            float2 Yk = cmul(Xk, g_kf[k]);
            float2 Yh = cmul(Xh, g_kf[hk]);
            float2 Yhc = cconj(Yh);
            float2 S = cscale(cadd(Yk, Yhc), 0.5f);
            float2 D = cscale(csub(Yk, Yhc), 0.5f);
            float2 u = cmul(cconj(w), D);
            float2 Zyk = make_float2(S.x - u.y, S.y + u.x);
            A[PD(k)] = cconj(Zyk);
            if (k != 4096) {
                float2 Ykc = cconj(Yk);
                float2 S2 = cscale(cadd(Yh, Ykc), 0.5f);
                float2 D2 = cscale(csub(Yh, Ykc), 0.5f);
                float2 v = cmul(w, D2);
                float2 Zyh = make_float2(S2.x + v.y, S2.y - v.x);
                A[PD(hk)] = cconj(Zyh);
            }
        }
    }
    __syncthreads();

    fft8192_r8<NTC, false, true>(A, B, tid);   // only low half of F needed

    float2* yr = (float2*)(y + (size_t)b * LSEQ);
    const float sc = 1.0f / 8192.0f;
    for (int j = tid; j < 4096; j += NTC) {
        float2 f = B[PD(j)];
        yr[j] = make_float2(f.x * sc, -f.y * sc);
    }
}

// ---------------- launch ----------------
extern "C" void kernel_launch(void* const* d_in, const int* in_sizes, int n_in,
                              void* d_out, int out_size) {
    const float* x  = (const float*)d_in[0];
    const float* Bv = (const float*)d_in[1];
    const float* Cv = (const float*)d_in[2];
    float* y = (float*)d_out;
    (void)in_sizes; (void)n_in; (void)out_size;

    const int smem = 2 * PDSZ * (int)sizeof(float2);   // 147456 B
    cudaFuncSetAttribute(kprep_kernel, cudaFuncAttributeMaxDynamicSharedMemorySize, smem);
    cudaFuncSetAttribute(conv_kernel,  cudaFuncAttributeMaxDynamicSharedMemorySize, smem);

    setup_kernel<<<4353, 64>>>(Bv, Cv);
    kprep_kernel<<<1, NTC, smem>>>();
    conv_kernel<<<NBATCH, NTC, smem>>>(x, y);
}

// round 8
// speedup vs baseline: 1.6777x; 1.6777x over previous
#include <cuda_runtime.h>
#include <math.h>

#define LSEQ   8192
#define NBATCH 1024
#define NT     512
#define NSTATE 64
#define PI_F 3.14159265358979323846f

__device__ float2 g_wm[16384];   // WM[k] = exp(-2*pi*i*k/16384)
__device__ float2 g_kh[4100];    // K_hat spectrum bins 0..4096
__device__ float2 g_kf[8200];    // rfft_16384 of padded K, bins 0..8192

// ---------------- complex helpers ----------------
static __device__ __forceinline__ float2 cmul(float2 a, float2 b) {
    return make_float2(a.x*b.x - a.y*b.y, a.x*b.y + a.y*b.x);
}
static __device__ __forceinline__ float2 cadd(float2 a, float2 b){ return make_float2(a.x+b.x, a.y+b.y); }
static __device__ __forceinline__ float2 csub(float2 a, float2 b){ return make_float2(a.x-b.x, a.y-b.y); }
static __device__ __forceinline__ float2 cconj(float2 a){ return make_float2(a.x, -a.y); }
static __device__ __forceinline__ float2 cscale(float2 a, float s){ return make_float2(a.x*s, a.y*s); }

// ---------------- merged setup (ALL fp32 — fp64 pipe on B300 is poison) ----------------
// blocks 0..4096: Cauchy K_hat (64 thr, one state per thread, shfl reduce).
// blocks 4097..4352: twiddle table via sincospif (exact at quadrant points).
__global__ void setup_kernel(const float* __restrict__ Bv, const float* __restrict__ Cv) {
    if (blockIdx.x > 4096) {
        int k = (blockIdx.x - 4097) * 64 + threadIdx.x;   // 0..16383
        float s, c;
        sincospif((float)k / 8192.0f, &s, &c);            // angle = 2*pi*k/16384
        g_wm[k] = make_float2(c, -s);
        return;
    }
    __shared__ float shg[5];
    __shared__ float wsum[2][8];
    int f = blockIdx.x;              // 0..4096
    int n = threadIdx.x;             // 0..63
    if (n == 0) {
        // fp32 sincos of theta = 2*pi*f/8192. At f=4096 theta=float(pi) ->
        // sin ~ -8.74e-8 (nonzero), so 1+omega != 0: no Nyquist NaN, and this
        // matches the fp32 reference's own near-cancellation behavior.
        float th = (2.0f * PI_F / 8192.0f) * (float)f;
        float s, c;
        sincosf(th, &s, &c);                              // omega = c + i s
        float nr = 1.0f - c, ni = -s;
        float dr = 1.0f + c, di = s;
        float dd = dr*dr + di*di;
        shg[0] = 20.0f * (nr*dr + ni*di) / dd;            // g = (2/dt)(1-w)/(1+w)
        shg[1] = 20.0f * (ni*dr - nr*di) / dd;
        shg[2] = dr; shg[3] = di; shg[4] = dd;
    }
    __syncthreads();
    float gr = shg[0], gi = shg[1];
    float er = gr + 0.5f;
    float ei = gi - PI_F * (float)n;
    float inv = 1.0f / (er*er + ei*ei);
    float ir =  er * inv, ii = -ei * inv;                 // 1/(g - Lambda_n)
    float b0 = Bv[n];
    float a0 = Cv[n];
    float p2 = (float)n + 0.5f;
    float p  = sqrtf(p2);
    float v00 = a0*b0, v01 = a0*p, v10 = p*b0, v11 = p2;
    float acc[8] = { v00*ir, v00*ii, v01*ir, v01*ii,
                     v10*ir, v10*ii, v11*ir, v11*ii };
    #pragma unroll
    for (int off = 16; off; off >>= 1) {
        #pragma unroll
        for (int t = 0; t < 8; t++)
            acc[t] += __shfl_down_sync(0xffffffffu, acc[t], off);
    }
    if ((n & 31) == 0) {
        #pragma unroll
        for (int t = 0; t < 8; t++) wsum[n >> 5][t] = acc[t];
    }
    __syncthreads();
    if (n == 0) {
        float k00r = wsum[0][0]+wsum[1][0], k00i = wsum[0][1]+wsum[1][1];
        float k01r = wsum[0][2]+wsum[1][2], k01i = wsum[0][3]+wsum[1][3];
        float k10r = wsum[0][4]+wsum[1][4], k10i = wsum[0][5]+wsum[1][5];
        float k11r = wsum[0][6]+wsum[1][6], k11i = wsum[0][7]+wsum[1][7];
        float ur = 1.0f + k11r, ui = k11i;
        float t1r = k01r*ur - k01i*ui, t1i = k01r*ui + k01i*ur;
        float t2r = t1r*k10r - t1i*k10i, t2i = t1r*k10i + t1i*k10r;
        float hr = k00r - t2r, hi = k00i - t2i;
        float dr = shg[2], di = shg[3], dd = shg[4];
        float c2r = 2.0f*dr/dd, c2i = -2.0f*di/dd;        // 2/(1+omega)
        g_kh[f] = make_float2(c2r*hr - c2i*hi, c2r*hi + c2i*hr);
    }
}

// ---------------- radix-8 Stockham FFT, N=8192, forward ----------------
// 4 radix-8 stages + final radix-2. Reads A, result in B (trailing sync).
// ZHI: input's upper half (idx>=4096) is known zero (skip loads).
// SKIPHI: skip storing outputs [4096,8192) of the final stage.
template<int NTH, bool ZHI, bool SKIPHI>
static __device__ __forceinline__ void fft8192_r8(float2* A, float2* B, int tid) {
    float2* src = A;
    float2* dst = B;
    #pragma unroll
    for (int st = 0; st < 4; st++) {
        const int ls = 3 * st;            // log2(s): 0,3,6,9
        const int s  = 1 << ls;           // 1,8,64,512
        #pragma unroll
        for (int it = 0; it < 1024 / NTH; it++) {
            int idx = tid + it * NTH;     // < 1024
            int p = idx >> ls;
            int q = idx & (s - 1);
            float2 x0 = src[idx];
            float2 x1 = src[idx + 1024];
            float2 x2 = src[idx + 2048];
            float2 x3 = src[idx + 3072];
            float2 x4, x5, x6, x7;
            if (ZHI && st == 0) {
                x4 = x5 = x6 = x7 = make_float2(0.f, 0.f);
            } else {
                x4 = src[idx + 4096];
                x5 = src[idx + 5120];
                x6 = src[idx + 6144];
                x7 = src[idx + 7168];
            }
            // DFT8
            float2 ea = cadd(x0, x4), em = csub(x0, x4);
            float2 eb = cadd(x2, x6), en = csub(x2, x6);
            float2 ej = make_float2(-en.y, en.x);
            float2 E0 = cadd(ea, eb), E1 = csub(em, ej);
            float2 E2 = csub(ea, eb), E3 = cadd(em, ej);
            float2 oa = cadd(x1, x5), om = csub(x1, x5);
            float2 ob = cadd(x3, x7), on = csub(x3, x7);
            float2 oj = make_float2(-on.y, on.x);
            float2 O0 = cadd(oa, ob), O1 = csub(om, oj);
            float2 O2 = csub(oa, ob), O3 = cadd(om, oj);
            const float C = 0.70710678118654752440f;
            float2 t0 = O0;
            float2 t1 = make_float2(C*(O1.x + O1.y), C*(O1.y - O1.x));   // w8^1*O1
            float2 t2 = make_float2(O2.y, -O2.x);                         // -i*O2
            float2 t3 = make_float2(C*(O3.y - O3.x), -C*(O3.x + O3.y));   // w8^3*O3
            float2 X0 = cadd(E0, t0), X4 = csub(E0, t0);
            float2 X1 = cadd(E1, t1), X5 = csub(E1, t1);
            float2 X2 = cadd(E2, t2), X6 = csub(E2, t2);
            float2 X3 = cadd(E3, t3), X7 = csub(E3, t3);
            // twiddles: w_j = exp(-2*pi*i*p*s*j/8192) = g_wm[2*p*s*j]
            int tw = (p << (ls + 1));       // 2*p*s
            float2 w1 = g_wm[tw];
            float2 w2 = cmul(w1, w1);
            float2 w3 = cmul(w2, w1);
            float2 w4 = cmul(w2, w2);
            float2 w5 = cmul(w3, w2);
            float2 w6 = cmul(w3, w3);
            float2 w7 = cmul(w4, w3);
            int o = q + (p << (ls + 3));    // q + 8*s*p
            dst[o]         = X0;
            dst[o + s]     = cmul(w1, X1);
            dst[o + 2*s]   = cmul(w2, X2);
            dst[o + 3*s]   = cmul(w3, X3);
            dst[o + 4*s]   = cmul(w4, X4);
            dst[o + 5*s]   = cmul(w5, X5);
            dst[o + 6*s]   = cmul(w6, X6);
            dst[o + 7*s]   = cmul(w7, X7);
        }
        __syncthreads();
        float2* t = src; src = dst; dst = t;
    }
    // After 4 swaps: src == A, dst == B. Final radix-2 (p=0, twiddle-free).
    #pragma unroll
    for (int it = 0; it < 4096 / NTH; it++) {
        int q = tid + it * NTH;
        float2 a = src[q], b = src[q + 4096];
        dst[q] = cadd(a, b);
        if (!SKIPHI) dst[q + 4096] = csub(a, b);
    }
    __syncthreads();
}

// ---------------- K preparation ----------------
__global__ void kprep_kernel() {
    extern __shared__ float2 sm[];
    float2* A = sm;
    float2* B = sm + 8192;
    int tid = threadIdx.x;

    // Hermitian-extend K_hat and conjugate (conj trick for inverse FFT)
    #pragma unroll
    for (int it = 0; it < 16; it++) {
        int f = tid + it * NT;
        float2 kh = (f <= 4096) ? g_kh[f] : g_kh[8192 - f];
        A[f] = (f <= 4096) ? cconj(kh) : kh;
    }
    __syncthreads();
    fft8192_r8<NT, false, false>(A, B, tid);
    // K[t] = B[t].x/8192 ; pack halves (upper half zero -> ZHI on next FFT)
    const float sc = 1.0f / 8192.0f;
    #pragma unroll
    for (int it = 0; it < 8; it++) {
        int j = tid + it * NT;   // j < 4096
        A[j] = make_float2(B[2*j].x * sc, B[2*j + 1].x * sc);
    }
    __syncthreads();
    fft8192_r8<NT, true, false>(A, B, tid);
    // Unpack to rfft_16384 bins 0..8192
    for (int k = tid; k <= 4096; k += NT) {
        if (k == 0) {
            float2 Z0 = B[0];
            g_kf[0]    = make_float2(Z0.x + Z0.y, 0.f);
            g_kf[8192] = make_float2(Z0.x - Z0.y, 0.f);
        } else {
            int hk = 8192 - k;
            float2 Zk  = B[k];
            float2 Zhc = cconj(B[hk]);
            float2 E  = cscale(cadd(Zk, Zhc), 0.5f);
            float2 Om = csub(Zk, Zhc);
            float2 O  = make_float2(0.5f * Om.y, -0.5f * Om.x);
            float2 w  = g_wm[k];
            g_kf[k] = cadd(E, cmul(w, O));
            if (k != 4096) {
                float2 wh = make_float2(-w.x, w.y);
                g_kf[hk] = cadd(cconj(E), cmul(wh, cconj(O)));
            }
        }
    }
}

// ---------------- main batched FFT convolution ----------------
__global__ void __launch_bounds__(NT, 1) conv_kernel(const float* __restrict__ x,
                                                     float* __restrict__ y) {
    extern __shared__ float2 sm[];
    float2* A = sm;
    float2* B = sm + 8192;
    int b = blockIdx.x;
    int tid = threadIdx.x;

    // pack two reals per complex; upper half unwritten (ZHI FFT skips it)
    const float2* xr = (const float2*)(x + (size_t)b * LSEQ);
    #pragma unroll
    for (int it = 0; it < 8; it++) {
        int j = tid + it * NT;   // j < 4096
        A[j] = xr[j];
    }
    __syncthreads();

    fft8192_r8<NT, true, false>(A, B, tid);   // Z in B

    // unpack -> multiply by Kf -> repack conj(Zy) into A
    for (int k = tid; k <= 4096; k += NT) {
        if (k == 0) {
            float2 Z0 = B[0];
            float X0 = Z0.x + Z0.y;
            float XH = Z0.x - Z0.y;
            float2 Y0 = cscale(g_kf[0], X0);
            float2 YH = cscale(g_kf[8192], XH);
            float2 Yhc = cconj(YH);
            float2 S = cscale(cadd(Y0, Yhc), 0.5f);
            float2 D = cscale(csub(Y0, Yhc), 0.5f);
            float2 Zy0 = make_float2(S.x - D.y, S.y + D.x);
            A[0] = cconj(Zy0);
        } else {
            int hk = 8192 - k;
            float2 Zk  = B[k];
            float2 Zhc = cconj(B[hk]);
            float2 E  = cscale(cadd(Zk, Zhc), 0.5f);
            float2 Om = csub(Zk, Zhc);
            float2 O  = make_float2(0.5f * Om.y, -0.5f * Om.x);
            float2 w  = g_wm[k];
            float2 Xk = cadd(E, cmul(w, O));
            float2 wh = make_float2(-w.x, w.y);
            float2 Xh = cadd(cconj(E), cmul(wh, cconj(O)));
            float2 Yk = cmul(Xk, g_kf[k]);
            float2 Yh = cmul(Xh, g_kf[hk]);
            float2 Yhc = cconj(Yh);
            float2 S = cscale(cadd(Yk, Yhc), 0.5f);
            float2 D = cscale(csub(Yk, Yhc), 0.5f);
            float2 u = cmul(cconj(w), D);
            float2 Zyk = make_float2(S.x - u.y, S.y + u.x);
            A[k] = cconj(Zyk);
            if (k != 4096) {
                float2 Ykc = cconj(Yk);
                float2 S2 = cscale(cadd(Yh, Ykc), 0.5f);
                float2 D2 = cscale(csub(Yh, Ykc), 0.5f);
                float2 v = cmul(w, D2);
                float2 Zyh = make_float2(S2.x + v.y, S2.y - v.x);
                A[hk] = cconj(Zyh);
            }
        }
    }
    __syncthreads();

    fft8192_r8<NT, false, true>(A, B, tid);   // only low half of F needed

    float2* yr = (float2*)(y + (size_t)b * LSEQ);
    const float sc = 1.0f / 8192.0f;
    #pragma unroll
    for (int it = 0; it < 8; it++) {
        int j = tid + it * NT;
        float2 f = B[j];
        yr[j] = make_float2(f.x * sc, -f.y * sc);
    }
}

// ---------------- launch ----------------
extern "C" void kernel_launch(void* const* d_in, const int* in_sizes, int n_in,
                              void* d_out, int out_size) {
    const float* x  = (const float*)d_in[0];
    const float* Bv = (const float*)d_in[1];
    const float* Cv = (const float*)d_in[2];
    float* y = (float*)d_out;
    (void)in_sizes; (void)n_in; (void)out_size;

    const int smem = 2 * 8192 * (int)sizeof(float2);   // 131072 B
    cudaFuncSetAttribute(kprep_kernel, cudaFuncAttributeMaxDynamicSharedMemorySize, smem);
    cudaFuncSetAttribute(conv_kernel,  cudaFuncAttributeMaxDynamicSharedMemorySize, smem);

    setup_kernel<<<4353, 64>>>(Bv, Cv);
    kprep_kernel<<<1, NT, smem>>>();
    conv_kernel<<<NBATCH, NT, smem>>>(x, y);
}